// round 6
// baseline (speedup 1.0000x reference)
#include <cuda_runtime.h>
#include <math.h>

// NeuralMJP: B rows, D=32 in, H=128 hidden, S=32 states.
// out[b,:] = table[argmax_s y_s], y = softmax(log(q_next+1e-12)+gumbel(u)),
// q_next from 3 MLP-softmaxes; table = decoder applied to one-hot rows.
//
// FAST kernel (fp32, packed f32x2 FMA, libdevice expf/logf): answer + top-2
// raw-score gap; gap < GAP_THRESH rows flagged.
// SLOW kernel (all-double, authoritative): winner/runner + true gap.
//   gap_d >= BAND_D -> double winner (fp32 reference provably agrees).
//   gap_d <  BAND_D -> LOWER index of {winner,runner}: matches jnp.argmax
//   first-index semantics if the reference hit an exact fp32 y-tie; fair
//   coin otherwise.

#define Bd 32
#define Hn 128
#define Sn 32
#define TPB 256
#define GAP_THRESH 3e-3f
#define BAND_D 4e-7
#define FLAG_CAP (1 << 20)

typedef unsigned long long u64;

__device__ __align__(16) float g_table[Sn * Bd];
__device__ int g_nflag;
__device__ unsigned g_flagged[FLAG_CAP];

__device__ __forceinline__ u64 pk2(float lo, float hi) {
    u64 r; asm("mov.b64 %0,{%1,%2};" : "=l"(r) : "f"(lo), "f"(hi)); return r;
}
__device__ __forceinline__ void upk2(u64 v, float& lo, float& hi) {
    asm("mov.b64 {%0,%1},%2;" : "=f"(lo), "=f"(hi) : "l"(v));
}
// Packed fp32x2 FMA (Blackwell): 2 IEEE fp32 FMAs per instruction.
__device__ __forceinline__ u64 ffma2(u64 a, u64 b, u64 c) {
    u64 d; asm("fma.rn.f32x2 %0,%1,%2,%3;" : "=l"(d) : "l"(a), "l"(b), "l"(c)); return d;
}

__global__ void nmjp_zero_kernel() {
    if (threadIdx.x == 0) g_nflag = 0;
}

// ---------------------------------------------------------------------------
// Decoder table (accurate fp32): hidden_j = relu(dec_w1[s,j] + db1[j]);
// table[s][d] = FFMA-chain_j(hidden_j * dec_w2[j,d]) + db2[d].
// ---------------------------------------------------------------------------
__global__ void nmjp_table_kernel(const float* __restrict__ dw1,
                                  const float* __restrict__ db1,
                                  const float* __restrict__ dw2,
                                  const float* __restrict__ db2) {
    int t = threadIdx.x;
    int s = t >> 5;
    int d = t & 31;
    float acc = 0.0f;
#pragma unroll 4
    for (int j = 0; j < Hn; j++) {
        float hj = fmaxf(__fadd_rn(dw1[s * Hn + j], db1[j]), 0.0f);
        acc = fmaf(hj, dw2[j * Sn + d], acc);
    }
    g_table[s * Bd + d] = __fadd_rn(acc, db2[d]);
}

// ---------------------------------------------------------------------------
// Fast-path MLP: packed f32x2 FFMA chains, ascending k, bias after GEMM.
// ---------------------------------------------------------------------------
__device__ __forceinline__ void mlp_logits(const u64* __restrict__ hpk,
                                           const float* __restrict__ w1,
                                           const float* __restrict__ b1,
                                           const float* __restrict__ w2,
                                           const float* __restrict__ b2,
                                           float* __restrict__ lg) {
    u64 acc[16];
#pragma unroll
    for (int p = 0; p < 16; p++) acc[p] = 0ull;

#pragma unroll 1
    for (int jc = 0; jc < Hn; jc += 4) {
        u64 ha = 0ull, hb = 0ull;
#pragma unroll
        for (int i = 0; i < Bd; i++) {
            ulonglong2 w = *(const ulonglong2*)(w1 + i * Hn + jc);
            ha = ffma2(hpk[i], w.x, ha);
            hb = ffma2(hpk[i], w.y, hb);
        }
        float h0, h1, h2, h3;
        upk2(ha, h0, h1);
        upk2(hb, h2, h3);
        h0 = fmaxf(__fadd_rn(h0, b1[jc + 0]), 0.0f);
        h1 = fmaxf(__fadd_rn(h1, b1[jc + 1]), 0.0f);
        h2 = fmaxf(__fadd_rn(h2, b1[jc + 2]), 0.0f);
        h3 = fmaxf(__fadd_rn(h3, b1[jc + 3]), 0.0f);
        u64 pj[4];
        pj[0] = pk2(h0, h0);
        pj[1] = pk2(h1, h1);
        pj[2] = pk2(h2, h2);
        pj[3] = pk2(h3, h3);
#pragma unroll
        for (int jj = 0; jj < 4; jj++) {
            const ulonglong2* wr = (const ulonglong2*)(w2 + (jc + jj) * Sn);
#pragma unroll
            for (int p = 0; p < 8; p++) {
                ulonglong2 w = wr[p];
                acc[2 * p]     = ffma2(pj[jj], w.x, acc[2 * p]);
                acc[2 * p + 1] = ffma2(pj[jj], w.y, acc[2 * p + 1]);
            }
        }
    }
#pragma unroll
    for (int p = 0; p < 16; p++) {
        float x, y;
        upk2(acc[p], x, y);
        lg[2 * p]     = __fadd_rn(x, b2[2 * p]);
        lg[2 * p + 1] = __fadd_rn(y, b2[2 * p + 1]);
    }
}

__device__ __forceinline__ void load_weights(
    float* sw1, float* sw2, float* sb1, float* sb2,
    const float* qw1, const float* qb1, const float* qw2, const float* qb2,
    const float* giw1, const float* gib1, const float* giw2, const float* gib2,
    const float* gow1, const float* gob1, const float* gow2, const float* gob2,
    int tid, int nthr) {
    const float* s1[3] = {qw1, giw1, gow1};
    const float* s2[3] = {qw2, giw2, gow2};
    const float* v1[3] = {qb1, gib1, gob1};
    const float* v2[3] = {qb2, gib2, gob2};
#pragma unroll
    for (int m = 0; m < 3; m++) {
        for (int i = tid; i < Bd * Hn; i += nthr) sw1[m * Bd * Hn + i] = s1[m][i];
        for (int i = tid; i < Hn * Sn; i += nthr) sw2[m * Hn * Sn + i] = s2[m][i];
        for (int i = tid; i < Hn; i += nthr) sb1[m * Hn + i] = v1[m][i];
        if (tid < Sn) sb2[m * Sn + tid] = v2[m][tid];
    }
}

__device__ __forceinline__ void pack_h(const float* __restrict__ h, int row,
                                       u64* hpk) {
    const float4* hr = (const float4*)(h + (size_t)row * Bd);
#pragma unroll
    for (int k = 0; k < 8; k++) {
        float4 v = hr[k];
        hpk[4 * k + 0] = pk2(v.x, v.x);
        hpk[4 * k + 1] = pk2(v.y, v.y);
        hpk[4 * k + 2] = pk2(v.z, v.z);
        hpk[4 * k + 3] = pk2(v.w, v.w);
    }
}

// ===========================================================================
// FAST kernel
// ===========================================================================
__device__ __forceinline__ float softmax32_fast(float* a) {
    float m = a[0];
#pragma unroll
    for (int s = 1; s < Sn; s++) m = fmaxf(m, a[s]);
    float z = 0.0f;
#pragma unroll
    for (int s = 0; s < Sn; s++) {
        float e = expf(__fadd_rn(a[s], -m));
        a[s] = e;
        z = __fadd_rn(z, e);
    }
    float qs = 0.0f;
#pragma unroll
    for (int s = 0; s < Sn; s++) {
        float v = __fdiv_rn(a[s], z);
        a[s] = v;
        qs = __fadd_rn(qs, v);
    }
    return qs;
}

__global__ __launch_bounds__(TPB, 1) void nmjp_fast_kernel(
    const float* __restrict__ h, const float* __restrict__ u,
    const float* __restrict__ qw1, const float* __restrict__ qb1,
    const float* __restrict__ qw2, const float* __restrict__ qb2,
    const float* __restrict__ giw1, const float* __restrict__ gib1,
    const float* __restrict__ giw2, const float* __restrict__ gib2,
    const float* __restrict__ gow1, const float* __restrict__ gob1,
    const float* __restrict__ gow2, const float* __restrict__ gob2,
    float* __restrict__ out, int B) {
    extern __shared__ float smem[];
    float* sw1 = smem;
    float* sw2 = sw1 + 3 * Bd * Hn;
    float* sb1 = sw2 + 3 * Hn * Sn;
    float* sb2 = sb1 + 3 * Hn;
    float* sq  = sb2 + 3 * Sn;  // TPB*33 per-thread q scratch

    load_weights(sw1, sw2, sb1, sb2, qw1, qb1, qw2, qb2, giw1, gib1, giw2,
                 gib2, gow1, gob1, gow2, gob2, threadIdx.x, TPB);
    __syncthreads();

    int row = blockIdx.x * TPB + threadIdx.x;
    if (row >= B) return;

    u64 hpk[Bd];
    pack_h(h, row, hpk);
    float* myq = sq + threadIdx.x * 33;

    float a[Sn];
    mlp_logits(hpk, sw1, sb1, sw2, sb2, a);
    float qsum = softmax32_fast(a);
#pragma unroll
    for (int s = 0; s < Sn; s++) myq[s] = a[s];
    mlp_logits(hpk, sw1 + Bd * Hn, sb1 + Hn, sw2 + Hn * Sn, sb2 + Sn, a);
    softmax32_fast(a);
    float gin[Sn];
#pragma unroll
    for (int s = 0; s < Sn; s++) gin[s] = a[s];
    mlp_logits(hpk, sw1 + 2 * Bd * Hn, sb1 + 2 * Hn, sw2 + 2 * Hn * Sn,
               sb2 + 2 * Sn, a);
    softmax32_fast(a);

    const float4* ur = (const float4*)(u + (size_t)row * Sn);
    float b1v = -3.4e38f, b2v = -3.4e38f;
    int b1i = 0;
#pragma unroll
    for (int k = 0; k < 8; k++) {
        float4 uv = ur[k];
        float uu[4] = {uv.x, uv.y, uv.z, uv.w};
#pragma unroll
        for (int c = 0; c < 4; c++) {
            int s = 4 * k + c;
            float qv = myq[s];
            float d1 = __fmul_rn(gin[s], __fadd_rn(qsum, -qv));
            float d2 = __fmul_rn(a[s], qv);
            float qn = __fadd_rn(qv, __fadd_rn(d1, d2));
            float g1 = logf(__fadd_rn(uu[c], 1e-20f));
            float gn = -logf(__fadd_rn(-g1, 1e-20f));
            float v = __fadd_rn(logf(__fadd_rn(qn, 1e-12f)), gn);
            if (v > b1v) { b2v = b1v; b1v = v; b1i = s; }
            else if (v > b2v) { b2v = v; }
        }
    }

    const float4* tr = (const float4*)(g_table + b1i * Bd);
    float4* orow = (float4*)(out + (size_t)row * Bd);
#pragma unroll
    for (int k = 0; k < 8; k++) orow[k] = tr[k];

    if (b1v - b2v < GAP_THRESH) {
        int idx = atomicAdd(&g_nflag, 1);
        if (idx < FLAG_CAP) g_flagged[idx] = (unsigned)row;
    }
}

// ===========================================================================
// SLOW kernel: full-double recompute of flagged rows.
// ===========================================================================
__device__ void mlp_logits_double(const double* __restrict__ hd,
                                  const float* __restrict__ w1,
                                  const float* __restrict__ b1,
                                  const float* __restrict__ w2,
                                  const float* __restrict__ b2,
                                  double* __restrict__ lg) {
    double acc[Sn];
#pragma unroll
    for (int s = 0; s < Sn; s++) acc[s] = 0.0;
    for (int j = 0; j < Hn; j++) {
        double hj = 0.0;
#pragma unroll
        for (int i = 0; i < Bd; i++) hj = fma(hd[i], (double)w1[i * Hn + j], hj);
        hj = hj + (double)b1[j];
        hj = hj > 0.0 ? hj : 0.0;
#pragma unroll
        for (int s = 0; s < Sn; s++) acc[s] = fma(hj, (double)w2[j * Sn + s], acc[s]);
    }
#pragma unroll
    for (int s = 0; s < Sn; s++) lg[s] = acc[s] + (double)b2[s];
}

__device__ double softmax32_double(double* a) {
    double m = a[0];
#pragma unroll
    for (int s = 1; s < Sn; s++) m = a[s] > m ? a[s] : m;
    double z = 0.0;
#pragma unroll
    for (int s = 0; s < Sn; s++) {
        double e = exp(a[s] - m);
        a[s] = e;
        z += e;
    }
    double qs = 0.0;
#pragma unroll
    for (int s = 0; s < Sn; s++) {
        a[s] = a[s] / z;
        qs += a[s];
    }
    return qs;
}

__global__ __launch_bounds__(128, 1) void nmjp_slow_kernel(
    const float* __restrict__ h, const float* __restrict__ u,
    const float* __restrict__ qw1, const float* __restrict__ qb1,
    const float* __restrict__ qw2, const float* __restrict__ qb2,
    const float* __restrict__ giw1, const float* __restrict__ gib1,
    const float* __restrict__ giw2, const float* __restrict__ gib2,
    const float* __restrict__ gow1, const float* __restrict__ gob1,
    const float* __restrict__ gow2, const float* __restrict__ gob2,
    float* __restrict__ out) {
    extern __shared__ float smem[];
    float* sw1 = smem;
    float* sw2 = sw1 + 3 * Bd * Hn;
    float* sb1 = sw2 + 3 * Hn * Sn;
    float* sb2 = sb1 + 3 * Hn;

    load_weights(sw1, sw2, sb1, sb2, qw1, qb1, qw2, qb2, giw1, gib1, giw2,
                 gib2, gow1, gob1, gow2, gob2, threadIdx.x, 128);
    __syncthreads();

    int n = g_nflag;
    if (n > FLAG_CAP) n = FLAG_CAP;

    const double EG = (double)(float)1e-20f;
    const double EP = (double)(float)1e-12f;

    for (int i = blockIdx.x * 128 + threadIdx.x; i < n; i += gridDim.x * 128) {
        int row = (int)g_flagged[i];
        double hd[Bd];
#pragma unroll
        for (int k = 0; k < Bd; k++) hd[k] = (double)h[(size_t)row * Bd + k];

        double q[Sn], gi[Sn], go[Sn];
        mlp_logits_double(hd, sw1, sb1, sw2, sb2, q);
        double qsum = softmax32_double(q);
        mlp_logits_double(hd, sw1 + Bd * Hn, sb1 + Hn, sw2 + Hn * Sn, sb2 + Sn, gi);
        softmax32_double(gi);
        mlp_logits_double(hd, sw1 + 2 * Bd * Hn, sb1 + 2 * Hn,
                          sw2 + 2 * Hn * Sn, sb2 + 2 * Sn, go);
        softmax32_double(go);

        double b1v = -1e300, b2v = -1e300;
        int b1i = 0, b2i = 0;
#pragma unroll
        for (int s = 0; s < Sn; s++) {
            double uu = (double)u[(size_t)row * Sn + s];
            double qv = q[s];
            double qn = qv + gi[s] * (qsum - qv) + go[s] * qv;
            double gn = -log(-log(uu + EG) + EG);
            double v = log(qn + EP) + gn;
            if (v > b1v) { b2v = b1v; b2i = b1i; b1v = v; b1i = s; }
            else if (v > b2v) { b2v = v; b2i = s; }
        }

        int best = b1i;
        if (b1v - b2v < BAND_D) best = (b1i < b2i) ? b1i : b2i;

        const float4* tr = (const float4*)(g_table + best * Bd);
        float4* orow = (float4*)(out + (size_t)row * Bd);
#pragma unroll
        for (int k = 0; k < 8; k++) orow[k] = tr[k];
    }
}

extern "C" void kernel_launch(void* const* d_in, const int* in_sizes, int n_in,
                              void* d_out, int out_size) {
    const float* h    = (const float*)d_in[0];
    const float* u    = (const float*)d_in[1];
    const float* qw1  = (const float*)d_in[2];
    const float* qb1  = (const float*)d_in[3];
    const float* qw2  = (const float*)d_in[4];
    const float* qb2  = (const float*)d_in[5];
    const float* giw1 = (const float*)d_in[6];
    const float* gib1 = (const float*)d_in[7];
    const float* giw2 = (const float*)d_in[8];
    const float* gib2 = (const float*)d_in[9];
    const float* gow1 = (const float*)d_in[10];
    const float* gob1 = (const float*)d_in[11];
    const float* gow2 = (const float*)d_in[12];
    const float* gob2 = (const float*)d_in[13];
    const float* dw1  = (const float*)d_in[14];
    const float* db1  = (const float*)d_in[15];
    const float* dw2  = (const float*)d_in[16];
    const float* db2  = (const float*)d_in[17];

    int B = in_sizes[0] / Bd;

    size_t smem_fast =
        (size_t)(3 * Bd * Hn + 3 * Hn * Sn + 3 * Hn + 3 * Sn + TPB * 33) * sizeof(float);
    size_t smem_slow =
        (size_t)(3 * Bd * Hn + 3 * Hn * Sn + 3 * Hn + 3 * Sn) * sizeof(float);
    cudaFuncSetAttribute(nmjp_fast_kernel,
                         cudaFuncAttributeMaxDynamicSharedMemorySize,
                         (int)smem_fast);
    cudaFuncSetAttribute(nmjp_slow_kernel,
                         cudaFuncAttributeMaxDynamicSharedMemorySize,
                         (int)smem_slow);

    nmjp_zero_kernel<<<1, 32>>>();
    nmjp_table_kernel<<<1, Sn * Bd>>>(dw1, db1, dw2, db2);

    int grid = (B + TPB - 1) / TPB;
    nmjp_fast_kernel<<<grid, TPB, smem_fast>>>(
        h, u, qw1, qb1, qw2, qb2, giw1, gib1, giw2, gib2,
        gow1, gob1, gow2, gob2, (float*)d_out, B);

    nmjp_slow_kernel<<<148, 128, smem_slow>>>(
        h, u, qw1, qb1, qw2, qb2, giw1, gib1, giw2, gib2,
        gow1, gob1, gow2, gob2, (float*)d_out);
}

// round 7
// speedup vs baseline: 1.0030x; 1.0030x over previous
#include <cuda_runtime.h>
#include <math.h>

// NeuralMJP: B rows, D=32 in, H=128 hidden, S=32 states.
// out[b,:] = table[argmax_s y_s]; fast fp32 kernel computes scores + top-2
// gap, rows with gap < GAP_THRESH re-resolved by an all-double slow kernel
// (winner unless true gap < BAND_D, then lower index = jnp.argmax tie rule).
// Fast kernel numeric ORDER is free (slow kernel owns knife rows), so it uses
// cross-packed f32x2 FMAs with transposed W1 and horizontal adds.

#define Bd 32
#define Hn 128
#define Sn 32
#define TPB 128
#define GAP_THRESH 3e-3f
#define BAND_D 4e-7
#define FLAG_CAP (1 << 20)

typedef unsigned long long u64;

__device__ __align__(16) float g_table[Sn * Bd];
__device__ int g_nflag;
__device__ unsigned g_flagged[FLAG_CAP];

__device__ __forceinline__ u64 pk2(float lo, float hi) {
    u64 r; asm("mov.b64 %0,{%1,%2};" : "=l"(r) : "f"(lo), "f"(hi)); return r;
}
__device__ __forceinline__ void upk2(u64 v, float& lo, float& hi) {
    asm("mov.b64 {%0,%1},%2;" : "=f"(lo), "=f"(hi) : "l"(v));
}
// Packed fp32x2 FMA (Blackwell): 2 IEEE fp32 FMAs per instruction.
__device__ __forceinline__ u64 ffma2(u64 a, u64 b, u64 c) {
    u64 d; asm("fma.rn.f32x2 %0,%1,%2,%3;" : "=l"(d) : "l"(a), "l"(b), "l"(c)); return d;
}

__global__ void nmjp_zero_kernel() {
    if (threadIdx.x == 0) g_nflag = 0;
}

// ---------------------------------------------------------------------------
// Decoder table: table[s][d] = relu(dec_w1[s,:]+db1) . dec_w2[:,d] + db2[d].
// ---------------------------------------------------------------------------
__global__ void nmjp_table_kernel(const float* __restrict__ dw1,
                                  const float* __restrict__ db1,
                                  const float* __restrict__ dw2,
                                  const float* __restrict__ db2) {
    int t = threadIdx.x;
    int s = t >> 5;
    int d = t & 31;
    float acc = 0.0f;
#pragma unroll 4
    for (int j = 0; j < Hn; j++) {
        float hj = fmaxf(__fadd_rn(dw1[s * Hn + j], db1[j]), 0.0f);
        acc = fmaf(hj, dw2[j * Sn + d], acc);
    }
    g_table[s * Bd + d] = __fadd_rn(acc, db2[d]);
}

// ===========================================================================
// FAST kernel: phased weights (one MLP staged at a time), cross-packed h.
// smem: w1t[128][32] (transposed W1), w2[128][32], b1[128], b2[32],
//       q scratch TPB*33 (padded).
// ===========================================================================
#define SM_W1T 0
#define SM_W2  (Bd * Hn)
#define SM_B1  (SM_W2 + Hn * Sn)
#define SM_B2  (SM_B1 + Hn)
#define SM_Q   (SM_B2 + Sn)
#define SM_TOT (SM_Q + TPB * 33)

// logits[32] for one MLP; hp = 16 u64 of (h_{2p}, h_{2p+1}).
__device__ __forceinline__ void mlp_logits_v2(const u64* __restrict__ hp,
                                              const float* __restrict__ sw1t,
                                              const float* __restrict__ sb1,
                                              const float* __restrict__ sw2,
                                              const float* __restrict__ sb2,
                                              float* __restrict__ lg) {
    u64 acc[16];
#pragma unroll
    for (int p = 0; p < 16; p++) acc[p] = 0ull;

#pragma unroll 2
    for (int j0 = 0; j0 < Hn; j0 += 4) {
        u64 c0 = 0ull, c1 = 0ull, c2 = 0ull, c3 = 0ull;
        const ulonglong2* r0 = (const ulonglong2*)(sw1t + (j0 + 0) * Bd);
        const ulonglong2* r1 = (const ulonglong2*)(sw1t + (j0 + 1) * Bd);
        const ulonglong2* r2 = (const ulonglong2*)(sw1t + (j0 + 2) * Bd);
        const ulonglong2* r3 = (const ulonglong2*)(sw1t + (j0 + 3) * Bd);
#pragma unroll
        for (int p = 0; p < 8; p++) {
            ulonglong2 w0 = r0[p], w1 = r1[p], w2 = r2[p], w3 = r3[p];
            c0 = ffma2(hp[2 * p], w0.x, c0);
            c1 = ffma2(hp[2 * p], w1.x, c1);
            c2 = ffma2(hp[2 * p], w2.x, c2);
            c3 = ffma2(hp[2 * p], w3.x, c3);
            c0 = ffma2(hp[2 * p + 1], w0.y, c0);
            c1 = ffma2(hp[2 * p + 1], w1.y, c1);
            c2 = ffma2(hp[2 * p + 1], w2.y, c2);
            c3 = ffma2(hp[2 * p + 1], w3.y, c3);
        }
        u64 hpj[4];
        {
            float lo, hi, hv;
            upk2(c0, lo, hi);
            hv = fmaxf(lo + hi + sb1[j0 + 0], 0.0f);
            hpj[0] = pk2(hv, hv);
            upk2(c1, lo, hi);
            hv = fmaxf(lo + hi + sb1[j0 + 1], 0.0f);
            hpj[1] = pk2(hv, hv);
            upk2(c2, lo, hi);
            hv = fmaxf(lo + hi + sb1[j0 + 2], 0.0f);
            hpj[2] = pk2(hv, hv);
            upk2(c3, lo, hi);
            hv = fmaxf(lo + hi + sb1[j0 + 3], 0.0f);
            hpj[3] = pk2(hv, hv);
        }
#pragma unroll
        for (int jj = 0; jj < 4; jj++) {
            const ulonglong2* wr = (const ulonglong2*)(sw2 + (j0 + jj) * Sn);
#pragma unroll
            for (int p = 0; p < 8; p++) {
                ulonglong2 w = wr[p];
                acc[2 * p]     = ffma2(hpj[jj], w.x, acc[2 * p]);
                acc[2 * p + 1] = ffma2(hpj[jj], w.y, acc[2 * p + 1]);
            }
        }
    }
#pragma unroll
    for (int p = 0; p < 16; p++) {
        float x, y;
        upk2(acc[p], x, y);
        lg[2 * p]     = x + sb2[2 * p];
        lg[2 * p + 1] = y + sb2[2 * p + 1];
    }
}

__device__ __forceinline__ float softmax32_fast(float* a) {
    float m = a[0];
#pragma unroll
    for (int s = 1; s < Sn; s++) m = fmaxf(m, a[s]);
    float z = 0.0f;
#pragma unroll
    for (int s = 0; s < Sn; s++) {
        float e = expf(a[s] - m);
        a[s] = e;
        z += e;
    }
    float inv = __fdiv_rn(1.0f, z);
    float qs = 0.0f;
#pragma unroll
    for (int s = 0; s < Sn; s++) {
        float v = a[s] * inv;
        a[s] = v;
        qs += v;
    }
    return qs;
}

__global__ __launch_bounds__(TPB, 3) void nmjp_fast_kernel(
    const float* __restrict__ h, const float* __restrict__ u,
    const float* __restrict__ qw1, const float* __restrict__ qb1,
    const float* __restrict__ qw2, const float* __restrict__ qb2,
    const float* __restrict__ giw1, const float* __restrict__ gib1,
    const float* __restrict__ giw2, const float* __restrict__ gib2,
    const float* __restrict__ gow1, const float* __restrict__ gob1,
    const float* __restrict__ gow2, const float* __restrict__ gob2,
    float* __restrict__ out, int B) {
    extern __shared__ float smem[];
    float* sw1t = smem + SM_W1T;
    float* sw2  = smem + SM_W2;
    float* sb1  = smem + SM_B1;
    float* sb2  = smem + SM_B2;
    float* myq  = smem + SM_Q + threadIdx.x * 33;

    const float* W1[3] = {qw1, giw1, gow1};
    const float* B1[3] = {qb1, gib1, gob1};
    const float* W2[3] = {qw2, giw2, gow2};
    const float* B2[3] = {qb2, gib2, gob2};

    int row = blockIdx.x * TPB + threadIdx.x;
    bool live = row < B;

    // h row, cross-packed (h_{2p}, h_{2p+1})
    u64 hp[16];
    if (live) {
        const float4* hr = (const float4*)(h + (size_t)row * Bd);
#pragma unroll
        for (int k = 0; k < 8; k++) {
            float4 v = hr[k];
            hp[2 * k]     = pk2(v.x, v.y);
            hp[2 * k + 1] = pk2(v.z, v.w);
        }
    }

    float t[Sn];
    float qsum = 0.0f;

#pragma unroll
    for (int m = 0; m < 3; m++) {
        // Stage MLP m weights (W1 transposed: sw1t[j*32+i] = w1[i*128+j]).
        {
            const float* w1 = W1[m];
            const float* w2 = W2[m];
            for (int idx = threadIdx.x; idx < Bd * Hn; idx += TPB) {
                int i = idx >> 7;
                int j = idx & 127;
                sw1t[j * Bd + i] = w1[idx];
            }
            for (int idx = threadIdx.x; idx < Hn * Sn; idx += TPB)
                sw2[idx] = w2[idx];
            sb1[threadIdx.x] = B1[m][threadIdx.x];  // TPB == Hn
            if (threadIdx.x < Sn) sb2[threadIdx.x] = B2[m][threadIdx.x];
        }
        __syncthreads();

        if (live) {
            float a[Sn];
            mlp_logits_v2(hp, sw1t, sb1, sw2, sb2, a);
            float ssum = softmax32_fast(a);
            if (m == 0) {
                qsum = ssum;
#pragma unroll
                for (int s = 0; s < Sn; s++) myq[s] = a[s];
            } else if (m == 1) {
#pragma unroll
                for (int s = 0; s < Sn; s++) {
                    float qv = myq[s];
                    t[s] = qv + a[s] * (qsum - qv);
                }
            } else {
                // scores + argmax + gap + output
                const float4* ur = (const float4*)(u + (size_t)row * Sn);
                float b1v = -3.4e38f, b2v = -3.4e38f;
                int b1i = 0;
#pragma unroll
                for (int k = 0; k < 8; k++) {
                    float4 uv = ur[k];
                    float uu[4] = {uv.x, uv.y, uv.z, uv.w};
#pragma unroll
                    for (int c = 0; c < 4; c++) {
                        int s = 4 * k + c;
                        float qn = fmaf(a[s], myq[s], t[s]);  // q_next
                        float g1 = logf(uu[c] + 1e-20f);
                        float gn = -logf(-g1 + 1e-20f);
                        float v = logf(qn + 1e-12f) + gn;
                        if (v > b1v) { b2v = b1v; b1v = v; b1i = s; }
                        else if (v > b2v) { b2v = v; }
                    }
                }
                const float4* tr = (const float4*)(g_table + b1i * Bd);
                float4* orow = (float4*)(out + (size_t)row * Bd);
#pragma unroll
                for (int k = 0; k < 8; k++) orow[k] = tr[k];
                if (b1v - b2v < GAP_THRESH) {
                    int idx = atomicAdd(&g_nflag, 1);
                    if (idx < FLAG_CAP) g_flagged[idx] = (unsigned)row;
                }
            }
        }
        if (m < 2) __syncthreads();
    }
}

// ===========================================================================
// SLOW kernel: full-double recompute of flagged rows (verified in R6).
// ===========================================================================
__device__ __forceinline__ void load_weights_rm(
    float* sw1, float* sw2, float* sb1, float* sb2,
    const float* qw1, const float* qb1, const float* qw2, const float* qb2,
    const float* giw1, const float* gib1, const float* giw2, const float* gib2,
    const float* gow1, const float* gob1, const float* gow2, const float* gob2,
    int tid, int nthr) {
    const float* s1[3] = {qw1, giw1, gow1};
    const float* s2[3] = {qw2, giw2, gow2};
    const float* v1[3] = {qb1, gib1, gob1};
    const float* v2[3] = {qb2, gib2, gob2};
#pragma unroll
    for (int m = 0; m < 3; m++) {
        for (int i = tid; i < Bd * Hn; i += nthr) sw1[m * Bd * Hn + i] = s1[m][i];
        for (int i = tid; i < Hn * Sn; i += nthr) sw2[m * Hn * Sn + i] = s2[m][i];
        for (int i = tid; i < Hn; i += nthr) sb1[m * Hn + i] = v1[m][i];
        if (tid < Sn) sb2[m * Sn + tid] = v2[m][tid];
    }
}

__device__ void mlp_logits_double(const double* __restrict__ hd,
                                  const float* __restrict__ w1,
                                  const float* __restrict__ b1,
                                  const float* __restrict__ w2,
                                  const float* __restrict__ b2,
                                  double* __restrict__ lg) {
    double acc[Sn];
#pragma unroll
    for (int s = 0; s < Sn; s++) acc[s] = 0.0;
    for (int j = 0; j < Hn; j++) {
        double hj = 0.0;
#pragma unroll
        for (int i = 0; i < Bd; i++) hj = fma(hd[i], (double)w1[i * Hn + j], hj);
        hj = hj + (double)b1[j];
        hj = hj > 0.0 ? hj : 0.0;
#pragma unroll
        for (int s = 0; s < Sn; s++) acc[s] = fma(hj, (double)w2[j * Sn + s], acc[s]);
    }
#pragma unroll
    for (int s = 0; s < Sn; s++) lg[s] = acc[s] + (double)b2[s];
}

__device__ double softmax32_double(double* a) {
    double m = a[0];
#pragma unroll
    for (int s = 1; s < Sn; s++) m = a[s] > m ? a[s] : m;
    double z = 0.0;
#pragma unroll
    for (int s = 0; s < Sn; s++) {
        double e = exp(a[s] - m);
        a[s] = e;
        z += e;
    }
    double qs = 0.0;
#pragma unroll
    for (int s = 0; s < Sn; s++) {
        a[s] = a[s] / z;
        qs += a[s];
    }
    return qs;
}

__global__ __launch_bounds__(128, 1) void nmjp_slow_kernel(
    const float* __restrict__ h, const float* __restrict__ u,
    const float* __restrict__ qw1, const float* __restrict__ qb1,
    const float* __restrict__ qw2, const float* __restrict__ qb2,
    const float* __restrict__ giw1, const float* __restrict__ gib1,
    const float* __restrict__ giw2, const float* __restrict__ gib2,
    const float* __restrict__ gow1, const float* __restrict__ gob1,
    const float* __restrict__ gow2, const float* __restrict__ gob2,
    float* __restrict__ out) {
    extern __shared__ float smem[];
    float* sw1 = smem;
    float* sw2 = sw1 + 3 * Bd * Hn;
    float* sb1 = sw2 + 3 * Hn * Sn;
    float* sb2 = sb1 + 3 * Hn;

    load_weights_rm(sw1, sw2, sb1, sb2, qw1, qb1, qw2, qb2, giw1, gib1, giw2,
                    gib2, gow1, gob1, gow2, gob2, threadIdx.x, 128);
    __syncthreads();

    int n = g_nflag;
    if (n > FLAG_CAP) n = FLAG_CAP;

    const double EG = (double)(float)1e-20f;
    const double EP = (double)(float)1e-12f;

    for (int i = blockIdx.x * 128 + threadIdx.x; i < n; i += gridDim.x * 128) {
        int row = (int)g_flagged[i];
        double hd[Bd];
#pragma unroll
        for (int k = 0; k < Bd; k++) hd[k] = (double)h[(size_t)row * Bd + k];

        double q[Sn], gi[Sn], go[Sn];
        mlp_logits_double(hd, sw1, sb1, sw2, sb2, q);
        double qsum = softmax32_double(q);
        mlp_logits_double(hd, sw1 + Bd * Hn, sb1 + Hn, sw2 + Hn * Sn, sb2 + Sn, gi);
        softmax32_double(gi);
        mlp_logits_double(hd, sw1 + 2 * Bd * Hn, sb1 + 2 * Hn,
                          sw2 + 2 * Hn * Sn, sb2 + 2 * Sn, go);
        softmax32_double(go);

        double b1v = -1e300, b2v = -1e300;
        int b1i = 0, b2i = 0;
#pragma unroll
        for (int s = 0; s < Sn; s++) {
            double uu = (double)u[(size_t)row * Sn + s];
            double qv = q[s];
            double qn = qv + gi[s] * (qsum - qv) + go[s] * qv;
            double gn = -log(-log(uu + EG) + EG);
            double v = log(qn + EP) + gn;
            if (v > b1v) { b2v = b1v; b2i = b1i; b1v = v; b1i = s; }
            else if (v > b2v) { b2v = v; b2i = s; }
        }

        int best = b1i;
        if (b1v - b2v < BAND_D) best = (b1i < b2i) ? b1i : b2i;

        const float4* tr = (const float4*)(g_table + best * Bd);
        float4* orow = (float4*)(out + (size_t)row * Bd);
#pragma unroll
        for (int k = 0; k < 8; k++) orow[k] = tr[k];
    }
}

extern "C" void kernel_launch(void* const* d_in, const int* in_sizes, int n_in,
                              void* d_out, int out_size) {
    const float* h    = (const float*)d_in[0];
    const float* u    = (const float*)d_in[1];
    const float* qw1  = (const float*)d_in[2];
    const float* qb1  = (const float*)d_in[3];
    const float* qw2  = (const float*)d_in[4];
    const float* qb2  = (const float*)d_in[5];
    const float* giw1 = (const float*)d_in[6];
    const float* gib1 = (const float*)d_in[7];
    const float* giw2 = (const float*)d_in[8];
    const float* gib2 = (const float*)d_in[9];
    const float* gow1 = (const float*)d_in[10];
    const float* gob1 = (const float*)d_in[11];
    const float* gow2 = (const float*)d_in[12];
    const float* gob2 = (const float*)d_in[13];
    const float* dw1  = (const float*)d_in[14];
    const float* db1  = (const float*)d_in[15];
    const float* dw2  = (const float*)d_in[16];
    const float* db2  = (const float*)d_in[17];

    int B = in_sizes[0] / Bd;

    size_t smem_fast = (size_t)SM_TOT * sizeof(float);
    size_t smem_slow =
        (size_t)(3 * Bd * Hn + 3 * Hn * Sn + 3 * Hn + 3 * Sn) * sizeof(float);
    cudaFuncSetAttribute(nmjp_fast_kernel,
                         cudaFuncAttributeMaxDynamicSharedMemorySize,
                         (int)smem_fast);
    cudaFuncSetAttribute(nmjp_slow_kernel,
                         cudaFuncAttributeMaxDynamicSharedMemorySize,
                         (int)smem_slow);

    nmjp_zero_kernel<<<1, 32>>>();
    nmjp_table_kernel<<<1, Sn * Bd>>>(dw1, db1, dw2, db2);

    int grid = (B + TPB - 1) / TPB;
    nmjp_fast_kernel<<<grid, TPB, smem_fast>>>(
        h, u, qw1, qb1, qw2, qb2, giw1, gib1, giw2, gib2,
        gow1, gob1, gow2, gob2, (float*)d_out, B);

    nmjp_slow_kernel<<<148, 128, smem_slow>>>(
        h, u, qw1, qb1, qw2, qb2, giw1, gib1, giw2, gib2,
        gow1, gob1, gow2, gob2, (float*)d_out);
}